// round 5
// baseline (speedup 1.0000x reference)
#include <cuda_runtime.h>
#include <cstdint>

// TransH scoring with cp.async-staged gathers.
// proj is linear => score = sum|proj(h + r - t)| with one projection per side.
// D = 128 floats = 32 float4. One warp per 2 rows; lane l stages & consumes
// its own 16B of each embedding row, so no block barrier is required.

#define D4 32                 // float4 per embedding row
#define ROWS_PER_BLOCK 8
#define THREADS 128           // 4 warps, 2 rows each

__device__ __forceinline__ void cp_async16(void* smem_dst, const void* gmem_src) {
    unsigned s = (unsigned)__cvta_generic_to_shared(smem_dst);
    asm volatile("cp.async.cg.shared.global [%0], [%1], 16;\n"
                 :: "r"(s), "l"(gmem_src) : "memory");
}

__global__ __launch_bounds__(THREADS)
void transh_kernel(const int* __restrict__ pos_h,
                   const int* __restrict__ pos_t,
                   const int* __restrict__ pos_r,
                   const int* __restrict__ neg_h,
                   const int* __restrict__ neg_t,
                   const int* __restrict__ neg_r,
                   const float4* __restrict__ ent,
                   const float4* __restrict__ vvrel,
                   const float4* __restrict__ bases,
                   float* __restrict__ out,
                   int n)
{
    // tile[row_local][emb][lane] : 8 * 7 * 32 * 16B = 28672 B
    __shared__ __align__(16) float4 tile[ROWS_PER_BLOCK * 7 * D4];

    const int tid  = threadIdx.x;
    const int warp = tid >> 5;
    const int lane = tid & 31;

    const int row_base = blockIdx.x * ROWS_PER_BLOCK + warp * 2;
    if (row_base >= n) return;

    // Clamp for safety on a ragged tail (n = 65536 divides evenly in practice).
    const int g0 = row_base;
    const int g1c = (row_base + 1 < n) ? row_base + 1 : row_base;

    // ---- indices (coalesced / L2-resident; uniform across the warp) ----
    const int ih0 = __ldg(&pos_h[g0]),  it0 = __ldg(&pos_t[g0]),  ir0 = __ldg(&pos_r[g0]);
    const int jh0 = __ldg(&neg_h[g0]),  jt0 = __ldg(&neg_t[g0]),  jr0 = __ldg(&neg_r[g0]);
    const int ih1 = __ldg(&pos_h[g1c]), it1 = __ldg(&pos_t[g1c]), ir1 = __ldg(&pos_r[g1c]);
    const int jh1 = __ldg(&neg_h[g1c]), jt1 = __ldg(&neg_t[g1c]), jr1 = __ldg(&neg_r[g1c]);

    // ---- stage all 14 embedding rows via cp.async (register-free MLP) ----
    float4* t0 = &tile[(warp * 2 + 0) * 7 * D4];
    float4* t1 = &tile[(warp * 2 + 1) * 7 * D4];

    cp_async16(&t0[0*D4 + lane], &bases[(size_t)ir0 * D4 + lane]);
    cp_async16(&t0[1*D4 + lane], &ent  [(size_t)ih0 * D4 + lane]);
    cp_async16(&t0[2*D4 + lane], &ent  [(size_t)it0 * D4 + lane]);
    cp_async16(&t0[3*D4 + lane], &vvrel[(size_t)ir0 * D4 + lane]);
    cp_async16(&t0[4*D4 + lane], &ent  [(size_t)jh0 * D4 + lane]);
    cp_async16(&t0[5*D4 + lane], &ent  [(size_t)jt0 * D4 + lane]);
    cp_async16(&t0[6*D4 + lane], &vvrel[(size_t)jr0 * D4 + lane]);

    cp_async16(&t1[0*D4 + lane], &bases[(size_t)ir1 * D4 + lane]);
    cp_async16(&t1[1*D4 + lane], &ent  [(size_t)ih1 * D4 + lane]);
    cp_async16(&t1[2*D4 + lane], &ent  [(size_t)it1 * D4 + lane]);
    cp_async16(&t1[3*D4 + lane], &vvrel[(size_t)ir1 * D4 + lane]);
    cp_async16(&t1[4*D4 + lane], &ent  [(size_t)jh1 * D4 + lane]);
    cp_async16(&t1[5*D4 + lane], &ent  [(size_t)jt1 * D4 + lane]);
    cp_async16(&t1[6*D4 + lane], &vvrel[(size_t)jr1 * D4 + lane]);

    asm volatile("cp.async.commit_group;" ::: "memory");
    asm volatile("cp.async.wait_group 0;" ::: "memory");
    __syncwarp();

    // ---- compute: two rows sequentially (keeps live regs ~7 float4) ----
    #pragma unroll
    for (int rr = 0; rr < 2; rr++) {
        const float4* b = (rr == 0) ? t0 : t1;

        const float4 v  = b[0*D4 + lane];
        const float4 ph = b[1*D4 + lane];
        const float4 pt = b[2*D4 + lane];
        const float4 pr = b[3*D4 + lane];
        const float4 nh = b[4*D4 + lane];
        const float4 nt = b[5*D4 + lane];
        const float4 nr = b[6*D4 + lane];

        float4 sp, sn;
        sp.x = ph.x + pr.x - pt.x;  sp.y = ph.y + pr.y - pt.y;
        sp.z = ph.z + pr.z - pt.z;  sp.w = ph.w + pr.w - pt.w;
        sn.x = nh.x + nr.x - nt.x;  sn.y = nh.y + nr.y - nt.y;
        sn.z = nh.z + nr.z - nt.z;  sn.w = nh.w + nr.w - nt.w;

        float dvv = v.x*v.x + v.y*v.y + v.z*v.z + v.w*v.w;
        float dvp = v.x*sp.x + v.y*sp.y + v.z*sp.z + v.w*sp.w;
        float dvn = v.x*sn.x + v.y*sn.y + v.z*sn.z + v.w*sn.w;

        #pragma unroll
        for (int o = 16; o > 0; o >>= 1) {
            dvv += __shfl_xor_sync(0xFFFFFFFFu, dvv, o);
            dvp += __shfl_xor_sync(0xFFFFFFFFu, dvp, o);
            dvn += __shfl_xor_sync(0xFFFFFFFFu, dvn, o);
        }

        const float inv = 1.0f / dvv;
        const float cp = dvp * inv;
        const float cn = dvn * inv;

        float ap = fabsf(sp.x - cp*v.x) + fabsf(sp.y - cp*v.y)
                 + fabsf(sp.z - cp*v.z) + fabsf(sp.w - cp*v.w);
        float an = fabsf(sn.x - cn*v.x) + fabsf(sn.y - cn*v.y)
                 + fabsf(sn.z - cn*v.z) + fabsf(sn.w - cn*v.w);

        #pragma unroll
        for (int o = 16; o > 0; o >>= 1) {
            ap += __shfl_xor_sync(0xFFFFFFFFu, ap, o);
            an += __shfl_xor_sync(0xFFFFFFFFu, an, o);
        }

        const int g = row_base + rr;
        if (lane == 0 && g < n) {
            out[g]     = ap;
            out[n + g] = an;
        }
    }
}

extern "C" void kernel_launch(void* const* d_in, const int* in_sizes, int n_in,
                              void* d_out, int out_size)
{
    const int*    pos_h = (const int*)d_in[0];
    const int*    pos_t = (const int*)d_in[1];
    const int*    pos_r = (const int*)d_in[2];
    const int*    neg_h = (const int*)d_in[3];
    const int*    neg_t = (const int*)d_in[4];
    const int*    neg_r = (const int*)d_in[5];
    const float4* ent   = (const float4*)d_in[6];
    const float4* vvrel = (const float4*)d_in[7];
    const float4* bases = (const float4*)d_in[8];
    float*        out   = (float*)d_out;

    const int n = in_sizes[0];  // 65536 rows
    const int blocks = (n + ROWS_PER_BLOCK - 1) / ROWS_PER_BLOCK;

    transh_kernel<<<blocks, THREADS>>>(pos_h, pos_t, pos_r,
                                       neg_h, neg_t, neg_r,
                                       ent, vvrel, bases, out, n);
}